// round 2
// baseline (speedup 1.0000x reference)
#include <cuda_runtime.h>
#include <cstddef>

#define KP1 6
#define KSEL 5
#define NUM_USERS 20000
#define EMBED_DIM 64
#define ALPHA_F 0.7f
#define NTHREADS 256

struct __align__(8) VI { float v; int i; };

__device__ __forceinline__ bool better(float av, int ai, float bv, int bi) {
    // Matches jax.lax.top_k ordering: descending value, ties -> lower index first.
    return (av > bv) || (av == bv && ai < bi);
}

__device__ __noinline__ void insert_slow(VI best[KP1], float v, int idx) {
    best[KP1 - 1].v = v;
    best[KP1 - 1].i = idx;
    #pragma unroll
    for (int j = KP1 - 1; j > 0; j--) {
        if (better(best[j].v, best[j].i, best[j - 1].v, best[j - 1].i)) {
            VI tmp = best[j]; best[j] = best[j - 1]; best[j - 1] = tmp;
        }
    }
}

__device__ __forceinline__ void insert_cand(VI best[KP1], float v, int idx) {
    // Fast path: one compare against the current 6th-best. Almost always rejects.
    if (better(v, idx, best[KP1 - 1].v, best[KP1 - 1].i)) {
        insert_slow(best, v, idx);
    }
}

__global__ __launch_bounds__(NTHREADS)
void user_blend_kernel(const int* __restrict__ user_idx,
                       const float* __restrict__ emb,
                       const float* __restrict__ cooc,
                       float* __restrict__ out)
{
    __shared__ VI s_lists[NTHREADS][KP1];     // 12 KB
    __shared__ float s_w[KSEL];
    __shared__ int   s_idx[KSEL];

    const int t = threadIdx.x;
    const int u = user_idx[blockIdx.x];
    const float4* __restrict__ row4 =
        reinterpret_cast<const float4*>(cooc + (size_t)u * NUM_USERS);

    VI best[KP1];
    #pragma unroll
    for (int j = 0; j < KP1; j++) { best[j].v = -3.0e38f; best[j].i = 0x7fffffff; }

    // 20000 / 4 = 5000 float4 elements; 256 threads -> ~20 iters each.
    #pragma unroll 4
    for (int i = t; i < NUM_USERS / 4; i += NTHREADS) {
        float4 f = row4[i];
        int base = i * 4;
        insert_cand(best, f.x, base + 0);
        insert_cand(best, f.y, base + 1);
        insert_cand(best, f.z, base + 2);
        insert_cand(best, f.w, base + 3);
    }

    #pragma unroll
    for (int j = 0; j < KP1; j++) s_lists[t][j] = best[j];
    __syncthreads();

    // Tree merge of per-thread top-6 lists.
    for (int stride = NTHREADS / 2; stride >= 1; stride >>= 1) {
        if (t < stride) {
            #pragma unroll
            for (int j = 0; j < KP1; j++) best[j] = s_lists[t][j];
            #pragma unroll
            for (int j = 0; j < KP1; j++) {
                VI o = s_lists[t + stride][j];
                insert_cand(best, o.v, o.i);
            }
            #pragma unroll
            for (int j = 0; j < KP1; j++) s_lists[t][j] = best[j];
        }
        __syncthreads();
    }

    // Thread 0: drop the max (slot 0), softmax over slots 1..5.
    if (t == 0) {
        float m = s_lists[0][1].v;                  // max of the 5 (list sorted desc)
        float e[KSEL];
        float sum = 0.0f;
        #pragma unroll
        for (int j = 0; j < KSEL; j++) {
            e[j] = __expf(s_lists[0][j + 1].v - m);
            sum += e[j];
        }
        float inv = 1.0f / sum;
        #pragma unroll
        for (int j = 0; j < KSEL; j++) {
            s_w[j]   = e[j] * inv;
            s_idx[j] = s_lists[0][j + 1].i;
        }
    }
    __syncthreads();

    if (t < EMBED_DIM) {
        float acc = 0.0f;
        #pragma unroll
        for (int j = 0; j < KSEL; j++)
            acc += s_w[j] * emb[(size_t)s_idx[j] * EMBED_DIM + t];
        float self = emb[(size_t)u * EMBED_DIM + t];
        out[(size_t)blockIdx.x * EMBED_DIM + t] = ALPHA_F * self + (1.0f - ALPHA_F) * acc;
    }
}

extern "C" void kernel_launch(void* const* d_in, const int* in_sizes, int n_in,
                              void* d_out, int out_size)
{
    // Identify inputs by element count:
    //   user_idx: 4096 (int32), emb: 20000*64 (f32), cooc: 20000*20000 (f32)
    const int*   user_idx = nullptr;
    const float* emb      = nullptr;
    const float* cooc     = nullptr;
    int batch = 0;
    for (int i = 0; i < n_in; i++) {
        long long sz = in_sizes[i];
        if (sz == (long long)NUM_USERS * NUM_USERS) {
            cooc = (const float*)d_in[i];
        } else if (sz == (long long)NUM_USERS * EMBED_DIM) {
            emb = (const float*)d_in[i];
        } else {
            user_idx = (const int*)d_in[i];
            batch = (int)sz;
        }
    }
    float* out = (float*)d_out;
    user_blend_kernel<<<batch, NTHREADS>>>(user_idx, emb, cooc, out);
}

// round 3
// speedup vs baseline: 8.1309x; 8.1309x over previous
#include <cuda_runtime.h>
#include <cstddef>

#define KP1 6
#define KSEL 5
#define NUM_USERS 20000
#define ROW4 (NUM_USERS / 4)       // 5000
#define EMBED_DIM 64
#define ALPHA_F 0.7f
#define NTHREADS 256
#define CAP 1024

struct __align__(8) VI { float v; int i; };

__device__ __forceinline__ bool better(float av, int ai, float bv, int bi) {
    // jax.lax.top_k order: descending value, ties -> lower index first.
    return (av > bv) || (av == bv && ai < bi);
}

__device__ __forceinline__ void exact_insert(VI best[KP1], float v, int idx) {
    if (better(v, idx, best[KP1 - 1].v, best[KP1 - 1].i)) {
        best[KP1 - 1].v = v;
        best[KP1 - 1].i = idx;
        #pragma unroll
        for (int j = KP1 - 1; j > 0; j--) {
            if (better(best[j].v, best[j].i, best[j - 1].v, best[j - 1].i)) {
                VI tmp = best[j]; best[j] = best[j - 1]; best[j - 1] = tmp;
            }
        }
    }
}

__global__ __launch_bounds__(NTHREADS)
void user_blend_kernel(const int* __restrict__ user_idx,
                       const float* __restrict__ emb,
                       const float* __restrict__ cooc,
                       float* __restrict__ out)
{
    __shared__ float s_red[NTHREADS];
    __shared__ float s_cval[CAP];
    __shared__ int   s_cidx[CAP];
    __shared__ int   s_count;
    __shared__ float s_T;
    __shared__ float s_w[KSEL];
    __shared__ int   s_idx[KSEL];

    const int t = threadIdx.x;
    const int u = user_idx[blockIdx.x];
    const float4* __restrict__ row4 =
        reinterpret_cast<const float4*>(cooc + (size_t)u * NUM_USERS);

    // ---------- Pass A: branchless per-thread max ----------
    float m0 = -3.0e38f, m1 = -3.0e38f;
    #pragma unroll 4
    for (int i = t; i < ROW4; i += NTHREADS) {
        float4 f = row4[i];
        m0 = fmaxf(m0, fmaxf(f.x, f.y));
        m1 = fmaxf(m1, fmaxf(f.z, f.w));
    }
    s_red[t] = fmaxf(m0, m1);
    if (t == 0) s_count = 0;
    __syncthreads();

    // T = 6th largest of the 256 thread maxes (safe lower bound on the
    // true 6th-largest element of the row).
    if (t == 0) {
        float top[KP1];
        #pragma unroll
        for (int j = 0; j < KP1; j++) top[j] = -3.0e38f;
        for (int k = 0; k < NTHREADS; k++) {
            float v = s_red[k];
            if (v > top[KP1 - 1]) {
                top[KP1 - 1] = v;
                #pragma unroll
                for (int j = KP1 - 1; j > 0; j--) {
                    if (top[j] > top[j - 1]) {
                        float tmp = top[j]; top[j] = top[j - 1]; top[j - 1] = tmp;
                    }
                }
            }
        }
        s_T = top[KP1 - 1];
    }
    __syncthreads();
    const float T = s_T;

    // ---------- Pass B: filtered candidate collection ----------
    #pragma unroll 4
    for (int i = t; i < ROW4; i += NTHREADS) {
        float4 f = row4[i];
        float m4 = fmaxf(fmaxf(f.x, f.y), fmaxf(f.z, f.w));
        if (m4 >= T) {                       // rarely taken
            int base = i * 4;
            if (f.x >= T) { int p = atomicAdd(&s_count, 1); if (p < CAP) { s_cval[p] = f.x; s_cidx[p] = base + 0; } }
            if (f.y >= T) { int p = atomicAdd(&s_count, 1); if (p < CAP) { s_cval[p] = f.y; s_cidx[p] = base + 1; } }
            if (f.z >= T) { int p = atomicAdd(&s_count, 1); if (p < CAP) { s_cval[p] = f.z; s_cidx[p] = base + 2; } }
            if (f.w >= T) { int p = atomicAdd(&s_count, 1); if (p < CAP) { s_cval[p] = f.w; s_cidx[p] = base + 3; } }
        }
    }
    __syncthreads();

    // ---------- Final exact top-6, softmax, weights ----------
    if (t == 0) {
        VI best[KP1];
        #pragma unroll
        for (int j = 0; j < KP1; j++) { best[j].v = -3.0e38f; best[j].i = 0x7fffffff; }

        int cnt = s_count;
        if (cnt <= CAP) {
            for (int k = 0; k < cnt; k++)
                exact_insert(best, s_cval[k], s_cidx[k]);
        } else {
            // Overflow fallback (adversarial ties only): serial exact scan.
            const float* row = cooc + (size_t)u * NUM_USERS;
            for (int k = 0; k < NUM_USERS; k++)
                exact_insert(best, row[k], k);
        }

        // Drop slot 0 (the max), softmax over slots 1..5.
        float m = best[1].v;
        float e[KSEL];
        float sum = 0.0f;
        #pragma unroll
        for (int j = 0; j < KSEL; j++) {
            e[j] = __expf(best[j + 1].v - m);
            sum += e[j];
        }
        float inv = 1.0f / sum;
        #pragma unroll
        for (int j = 0; j < KSEL; j++) {
            s_w[j]   = e[j] * inv;
            s_idx[j] = best[j + 1].i;
        }
    }
    __syncthreads();

    // ---------- Blend ----------
    if (t < EMBED_DIM) {
        float acc = 0.0f;
        #pragma unroll
        for (int j = 0; j < KSEL; j++)
            acc += s_w[j] * emb[(size_t)s_idx[j] * EMBED_DIM + t];
        float self = emb[(size_t)u * EMBED_DIM + t];
        out[(size_t)blockIdx.x * EMBED_DIM + t] = ALPHA_F * self + (1.0f - ALPHA_F) * acc;
    }
}

extern "C" void kernel_launch(void* const* d_in, const int* in_sizes, int n_in,
                              void* d_out, int out_size)
{
    // Identify inputs by element count:
    //   user_idx: 4096 (int32), emb: 20000*64 (f32), cooc: 20000*20000 (f32)
    const int*   user_idx = nullptr;
    const float* emb      = nullptr;
    const float* cooc     = nullptr;
    int batch = 0;
    for (int i = 0; i < n_in; i++) {
        long long sz = in_sizes[i];
        if (sz == (long long)NUM_USERS * NUM_USERS) {
            cooc = (const float*)d_in[i];
        } else if (sz == (long long)NUM_USERS * EMBED_DIM) {
            emb = (const float*)d_in[i];
        } else {
            user_idx = (const int*)d_in[i];
            batch = (int)sz;
        }
    }
    float* out = (float*)d_out;
    user_blend_kernel<<<batch, NTHREADS>>>(user_idx, emb, cooc, out);
}